// round 1
// baseline (speedup 1.0000x reference)
#include <cuda_runtime.h>
#include <math.h>

// Problem constants
#define BQ   2
#define SEQ  2048
#define DIM  1024
#define NH   16
#define HDIM 64
#define MROWS (BQ * SEQ)   // 4096

// Scratch (device globals: allocation-free)
__device__ float g_Q[MROWS * DIM];
__device__ float g_K[MROWS * DIM];
__device__ float g_V[MROWS * DIM];
__device__ float g_A[MROWS * DIM];

// ---------------------------------------------------------------------------
// GEMM: Y[4096,1024] = X[4096,1024] @ W[1024,1024] (+ bias)
// 128x128 block tile, BK=16, 256 threads, 8x8 per-thread tile.
// ---------------------------------------------------------------------------
__device__ __forceinline__ void gemm_body(const float* __restrict__ X,
                                          const float* __restrict__ W,
                                          const float* __restrict__ bias,
                                          float* __restrict__ Y) {
    __shared__ float As[16][132];  // transposed A tile, padded (2-way max on stores)
    __shared__ float Bs[16][128];

    const int tid = threadIdx.x;
    const int tx = tid & 15;
    const int ty = tid >> 4;
    const int row0 = blockIdx.y * 128;
    const int col0 = blockIdx.x * 128;

    float acc[8][8];
#pragma unroll
    for (int a = 0; a < 8; a++)
#pragma unroll
        for (int b = 0; b < 8; b++) acc[a][b] = 0.f;

    for (int kt = 0; kt < DIM; kt += 16) {
#pragma unroll
        for (int i = 0; i < 2; i++) {
            int idx = tid + i * 256;
            // A tile: 128 rows x 16 cols -> transposed store
            int ar = idx >> 2;
            int ac = (idx & 3) << 2;
            float4 v = *(const float4*)(X + (size_t)(row0 + ar) * DIM + kt + ac);
            As[ac + 0][ar] = v.x;
            As[ac + 1][ar] = v.y;
            As[ac + 2][ar] = v.z;
            As[ac + 3][ar] = v.w;
            // B tile: 16 rows x 128 cols
            int br = idx >> 5;
            int bc = (idx & 31) << 2;
            *(float4*)&Bs[br][bc] =
                *(const float4*)(W + (size_t)(kt + br) * DIM + col0 + bc);
        }
        __syncthreads();
#pragma unroll
        for (int k = 0; k < 16; k++) {
            float4 a0 = *(const float4*)&As[k][ty * 8];
            float4 a1 = *(const float4*)&As[k][ty * 8 + 4];
            float4 b0 = *(const float4*)&Bs[k][tx * 8];
            float4 b1 = *(const float4*)&Bs[k][tx * 8 + 4];
            float ra[8] = {a0.x, a0.y, a0.z, a0.w, a1.x, a1.y, a1.z, a1.w};
            float rb[8] = {b0.x, b0.y, b0.z, b0.w, b1.x, b1.y, b1.z, b1.w};
#pragma unroll
            for (int a = 0; a < 8; a++)
#pragma unroll
                for (int b = 0; b < 8; b++)
                    acc[a][b] = fmaf(ra[a], rb[b], acc[a][b]);
        }
        __syncthreads();
    }

#pragma unroll
    for (int a = 0; a < 8; a++) {
        int gr = row0 + ty * 8 + a;
#pragma unroll
        for (int c = 0; c < 2; c++) {
            int gc = col0 + tx * 8 + c * 4;
            float4 r;
            r.x = acc[a][c * 4 + 0];
            r.y = acc[a][c * 4 + 1];
            r.z = acc[a][c * 4 + 2];
            r.w = acc[a][c * 4 + 3];
            if (bias) {
                r.x += bias[gc + 0];
                r.y += bias[gc + 1];
                r.z += bias[gc + 2];
                r.w += bias[gc + 3];
            }
            *(float4*)(Y + (size_t)gr * DIM + gc) = r;
        }
    }
}

__global__ __launch_bounds__(256) void qkv_gemm_kernel(
    const float* __restrict__ X, const float* __restrict__ Wq,
    const float* __restrict__ Wk, const float* __restrict__ Wv,
    const float* __restrict__ bq, const float* __restrict__ bk) {
    const int z = blockIdx.z;
    const float* W = (z == 0) ? Wq : (z == 1) ? Wk : Wv;
    const float* bias = (z == 0) ? bq : (z == 1) ? bk : nullptr;
    float* Y = (z == 0) ? g_Q : (z == 1) ? g_K : g_V;
    gemm_body(X, W, bias, Y);
}

__global__ __launch_bounds__(256) void out_gemm_kernel(
    const float* __restrict__ Wo, const float* __restrict__ bo,
    float* __restrict__ out) {
    gemm_body(g_A, Wo, bo, out);
}

// ---------------------------------------------------------------------------
// Flash attention, causal + ALiBi-style key bias.
// i-tile = 128 rows, j-tile = 128 cols, HD = 64. 256 threads.
// The stochastic soft mask (mean -1e9, std 1e8) underflows exp() to exactly 0
// in fp32 -> equivalent to a hard causal mask.
// ---------------------------------------------------------------------------
struct AttnSmem {
    float Qt[64][128];   // transposed Q [d][i], XOR-swizzled
    float Kt[64][128];   // transposed K [d][j], XOR-swizzled
    float Vs[128][64];   // V [j][d]
    float Ps[128][132];  // probabilities [i][j], padded
};

__global__ __launch_bounds__(256, 1) void attn_kernel() {
    extern __shared__ char smraw[];
    AttnSmem& sm = *reinterpret_cast<AttnSmem*>(smraw);

    const int tid = threadIdx.x;
    const int tx = tid & 15;
    const int ty = tid >> 4;
    const int it = 15 - (int)blockIdx.x;  // heavy tiles first
    const int bh = blockIdx.y;
    const int b = bh >> 4;
    const int h = bh & 15;
    const int i0 = it * 128;
    const float slope = exp2f(-0.5f * (float)(h + 1));

    const size_t base = (size_t)(b * SEQ) * DIM + (size_t)h * HDIM;
    const float* Qg = g_Q + base + (size_t)i0 * DIM;

    // Load Q transposed+swizzled: element (d, i) stored at col ((i>>2)^((d>>2)&7))<<2 | (i&3)
    for (int idx = tid; idx < 128 * 16; idx += 256) {
        int r = idx >> 4;           // sequence row
        int c4 = (idx & 15) << 2;   // head-dim base
        float4 v = *(const float4*)(Qg + (size_t)r * DIM + c4);
        int sw = (c4 >> 2) & 7;
        int col = ((((r >> 2) ^ sw) << 2) | (r & 3));
        sm.Qt[c4 + 0][col] = v.x;
        sm.Qt[c4 + 1][col] = v.y;
        sm.Qt[c4 + 2][col] = v.z;
        sm.Qt[c4 + 3][col] = v.w;
    }

    float m[8], l[8], acc[8][4];
#pragma unroll
    for (int a = 0; a < 8; a++) {
        m[a] = -1e30f;
        l[a] = 0.f;
        acc[a][0] = acc[a][1] = acc[a][2] = acc[a][3] = 0.f;
    }

    const int ibase = 8 * ty;  // this thread's local query rows: ibase..ibase+7

    for (int jt = 0; jt <= it; jt++) {
        const int j0 = jt * 128;
        const float* Kg = g_K + base + (size_t)j0 * DIM;
        const float* Vg = g_V + base + (size_t)j0 * DIM;

        __syncthreads();  // previous PV / Q-load done before refill
        for (int idx = tid; idx < 128 * 16; idx += 256) {
            int r = idx >> 4;
            int c4 = (idx & 15) << 2;
            float4 kv = *(const float4*)(Kg + (size_t)r * DIM + c4);
            int sw = (c4 >> 2) & 7;
            int col = ((((r >> 2) ^ sw) << 2) | (r & 3));
            sm.Kt[c4 + 0][col] = kv.x;
            sm.Kt[c4 + 1][col] = kv.y;
            sm.Kt[c4 + 2][col] = kv.z;
            sm.Kt[c4 + 3][col] = kv.w;
            float4 vv = *(const float4*)(Vg + (size_t)r * DIM + c4);
            *(float4*)&sm.Vs[r][c4] = vv;
        }
        __syncthreads();

        // ---- S = Q K^T over d (outer-product form) ----
        // thread j columns: 4tx..4tx+3 (bb 0..3) and 64+4tx..64+4tx+3 (bb 4..7)
        float s[8][8];
#pragma unroll
        for (int a = 0; a < 8; a++)
#pragma unroll
            for (int bb = 0; bb < 8; bb++) s[a][bb] = 0.f;

#pragma unroll 8
        for (int d = 0; d < 64; d++) {
            const int sw = (d >> 2) & 7;
            const float* qrow = sm.Qt[d];
            const float* krow = sm.Kt[d];
            float4 q0 = *(const float4*)(qrow + (((2 * ty) ^ sw) << 2));
            float4 q1 = *(const float4*)(qrow + (((2 * ty + 1) ^ sw) << 2));
            float4 k0 = *(const float4*)(krow + ((tx ^ sw) << 2));
            float4 k1 = *(const float4*)(krow + (((tx + 16) ^ sw) << 2));
            float qa[8] = {q0.x, q0.y, q0.z, q0.w, q1.x, q1.y, q1.z, q1.w};
            float kb[8] = {k0.x, k0.y, k0.z, k0.w, k1.x, k1.y, k1.z, k1.w};
#pragma unroll
            for (int a = 0; a < 8; a++)
#pragma unroll
                for (int bb = 0; bb < 8; bb++)
                    s[a][bb] = fmaf(qa[a], kb[bb], s[a][bb]);
        }

        // ---- online softmax (scale + ALiBi bias + causal mask) ----
        const bool diag = (jt == it);
#pragma unroll
        for (int a = 0; a < 8; a++) {
            const int il = ibase + a;
            float rm = -1e30f;
#pragma unroll
            for (int bb = 0; bb < 8; bb++) {
                int jl = 4 * tx + (bb & 3) + ((bb >> 2) << 6);
                float v = s[a][bb] * 0.125f - slope * (float)(j0 + jl);
                if (diag && jl > il) v = -1e30f;  // hard causal mask (see theory)
                s[a][bb] = v;
                rm = fmaxf(rm, v);
            }
#pragma unroll
            for (int o = 8; o > 0; o >>= 1)
                rm = fmaxf(rm, __shfl_xor_sync(0xffffffffu, rm, o, 16));
            float mn = fmaxf(m[a], rm);
            float corr = __expf(m[a] - mn);
            m[a] = mn;
            float rs = 0.f;
#pragma unroll
            for (int bb = 0; bb < 8; bb++) {
                float p = __expf(s[a][bb] - mn);
                s[a][bb] = p;
                rs += p;
            }
#pragma unroll
            for (int o = 8; o > 0; o >>= 1)
                rs += __shfl_xor_sync(0xffffffffu, rs, o, 16);
            l[a] = l[a] * corr + rs;
            acc[a][0] *= corr;
            acc[a][1] *= corr;
            acc[a][2] *= corr;
            acc[a][3] *= corr;
        }

        // ---- write P to smem ----
#pragma unroll
        for (int a = 0; a < 8; a++) {
            *(float4*)&sm.Ps[ibase + a][4 * tx] =
                make_float4(s[a][0], s[a][1], s[a][2], s[a][3]);
            *(float4*)&sm.Ps[ibase + a][64 + 4 * tx] =
                make_float4(s[a][4], s[a][5], s[a][6], s[a][7]);
        }
        __syncthreads();

        // ---- O += P V  (thread d-cols: 4tx..4tx+3) ----
#pragma unroll 4
        for (int j4 = 0; j4 < 32; j4++) {
            float4 v0 = *(const float4*)&sm.Vs[4 * j4 + 0][4 * tx];
            float4 v1 = *(const float4*)&sm.Vs[4 * j4 + 1][4 * tx];
            float4 v2 = *(const float4*)&sm.Vs[4 * j4 + 2][4 * tx];
            float4 v3 = *(const float4*)&sm.Vs[4 * j4 + 3][4 * tx];
#pragma unroll
            for (int a = 0; a < 8; a++) {
                float4 p = *(const float4*)&sm.Ps[ibase + a][4 * j4];
                acc[a][0] = fmaf(p.x, v0.x, fmaf(p.y, v1.x, fmaf(p.z, v2.x, fmaf(p.w, v3.x, acc[a][0]))));
                acc[a][1] = fmaf(p.x, v0.y, fmaf(p.y, v1.y, fmaf(p.z, v2.y, fmaf(p.w, v3.y, acc[a][1]))));
                acc[a][2] = fmaf(p.x, v0.z, fmaf(p.y, v1.z, fmaf(p.z, v2.z, fmaf(p.w, v3.z, acc[a][2]))));
                acc[a][3] = fmaf(p.x, v0.w, fmaf(p.y, v1.w, fmaf(p.z, v2.w, fmaf(p.w, v3.w, acc[a][3]))));
            }
        }
    }

    // ---- normalize + store (layout already [b, i, h, d] = [B,S,D]) ----
    float* Og = g_A + base + (size_t)i0 * DIM;
#pragma unroll
    for (int a = 0; a < 8; a++) {
        float inv = 1.0f / l[a];
        float4 o = make_float4(acc[a][0] * inv, acc[a][1] * inv,
                               acc[a][2] * inv, acc[a][3] * inv);
        *(float4*)(Og + (size_t)(ibase + a) * DIM + 4 * tx) = o;
    }
}

// ---------------------------------------------------------------------------
extern "C" void kernel_launch(void* const* d_in, const int* in_sizes, int n_in,
                              void* d_out, int out_size) {
    const float* X  = (const float*)d_in[0];
    const float* Wq = (const float*)d_in[1];
    const float* bq = (const float*)d_in[2];
    const float* Wk = (const float*)d_in[3];
    const float* bk = (const float*)d_in[4];
    const float* Wv = (const float*)d_in[5];
    const float* Wo = (const float*)d_in[6];
    const float* bo = (const float*)d_in[7];
    float* out = (float*)d_out;

    // host-side attribute set (not a stream op; capture-safe, idempotent)
    cudaFuncSetAttribute(attn_kernel, cudaFuncAttributeMaxDynamicSharedMemorySize,
                         (int)sizeof(AttnSmem));

    // Q/K/V projections (z selects matrix)
    qkv_gemm_kernel<<<dim3(DIM / 128, MROWS / 128, 3), 256>>>(X, Wq, Wk, Wv, bq, bk);

    // attention (16 i-tiles x 32 batch*head)
    attn_kernel<<<dim3(SEQ / 128, BQ * NH), 256, sizeof(AttnSmem)>>>();

    // output projection
    out_gemm_kernel<<<dim3(DIM / 128, MROWS / 128, 1), 256>>>(Wo, bo, out);
}

// round 3
// speedup vs baseline: 1.6454x; 1.6454x over previous
#include <cuda_runtime.h>
#include <cuda_bf16.h>
#include <math.h>
#include <stdint.h>

// Problem constants
#define BQ   2
#define SEQ  2048
#define DIM  1024
#define NH   16
#define HDIM 64
#define MROWS (BQ * SEQ)   // 4096

// Scratch (device globals: allocation-free)
__device__ float g_Q[MROWS * DIM];
__device__ float g_K[MROWS * DIM];
__device__ float g_V[MROWS * DIM];
__device__ float g_A[MROWS * DIM];

__device__ __nv_bfloat16 gXhi[MROWS * DIM];
__device__ __nv_bfloat16 gXlo[MROWS * DIM];
__device__ __nv_bfloat16 gAhi[MROWS * DIM];
__device__ __nv_bfloat16 gAlo[MROWS * DIM];
__device__ __nv_bfloat16 gWhi[4 * DIM * DIM];
__device__ __nv_bfloat16 gWlo[4 * DIM * DIM];

// ---------------------------------------------------------------------------
// Helpers
// ---------------------------------------------------------------------------
__device__ __forceinline__ uint32_t smem_u32(const void* p) {
    uint32_t a;
    asm("{ .reg .u64 t; cvta.to.shared.u64 t, %1; cvt.u32.u64 %0, t; }"
        : "=r"(a) : "l"(p));
    return a;
}

__device__ __forceinline__ void cp16(uint32_t dst, const void* src) {
    asm volatile("cp.async.cg.shared.global [%0], [%1], 16;"
                 :: "r"(dst), "l"(__cvta_generic_to_global(src)));
}
__device__ __forceinline__ void cp_commit() {
    asm volatile("cp.async.commit_group;" ::: "memory");
}

__device__ __forceinline__ void ldsm4(uint32_t* r, uint32_t addr) {
    asm volatile("ldmatrix.sync.aligned.m8n8.x4.shared.b16 {%0,%1,%2,%3}, [%4];"
                 : "=r"(r[0]), "=r"(r[1]), "=r"(r[2]), "=r"(r[3]) : "r"(addr));
}
__device__ __forceinline__ void ldsm4t(uint32_t* r, uint32_t addr) {
    asm volatile("ldmatrix.sync.aligned.m8n8.x4.trans.shared.b16 {%0,%1,%2,%3}, [%4];"
                 : "=r"(r[0]), "=r"(r[1]), "=r"(r[2]), "=r"(r[3]) : "r"(addr));
}
__device__ __forceinline__ void mma16816(float* c, const uint32_t* a, const uint32_t* b) {
    asm volatile(
        "mma.sync.aligned.m16n8k16.row.col.f32.bf16.bf16.f32 "
        "{%0,%1,%2,%3}, {%4,%5,%6,%7}, {%8,%9}, {%0,%1,%2,%3};"
        : "+f"(c[0]), "+f"(c[1]), "+f"(c[2]), "+f"(c[3])
        : "r"(a[0]), "r"(a[1]), "r"(a[2]), "r"(a[3]), "r"(b[0]), "r"(b[1]));
}

__device__ __forceinline__ void bf16_split(float x, __nv_bfloat16& hi, __nv_bfloat16& lo) {
    hi = __float2bfloat16_rn(x);
    lo = __float2bfloat16_rn(x - __bfloat162float(hi));
}

// ---------------------------------------------------------------------------
// Convert fp32 -> bf16 hi/lo pairs (X and the 4 weight matrices)
// ---------------------------------------------------------------------------
__global__ __launch_bounds__(256) void convert_inputs(
    const float* __restrict__ X, const float* __restrict__ Wq,
    const float* __restrict__ Wk, const float* __restrict__ Wv,
    const float* __restrict__ Wo) {
    const int XQ = MROWS * DIM / 4;          // 1M float4
    const int WQ = DIM * DIM / 4;            // 256K float4 per W
    const int total4 = XQ + 4 * WQ;          // 2M
    for (int i = blockIdx.x * blockDim.x + threadIdx.x; i < total4;
         i += gridDim.x * blockDim.x) {
        const float* src;
        __nv_bfloat16 *dh, *dl;
        if (i < XQ) {
            int e = i * 4;
            src = X + e; dh = gXhi + e; dl = gXlo + e;
        } else {
            int t = i - XQ;
            int w = t / WQ;
            int off = (t - w * WQ) * 4;
            src = (w == 0) ? Wq + off : (w == 1) ? Wk + off
                  : (w == 2) ? Wv + off : Wo + off;
            dh = gWhi + (size_t)w * DIM * DIM + off;
            dl = gWlo + (size_t)w * DIM * DIM + off;
        }
        float4 v = *(const float4*)src;
        __nv_bfloat16 hx, lx, hy, ly, hz, lz, hw, lw;
        bf16_split(v.x, hx, lx);
        bf16_split(v.y, hy, ly);
        bf16_split(v.z, hz, lz);
        bf16_split(v.w, hw, lw);
        ((__nv_bfloat162*)dh)[0] = __nv_bfloat162(hx, hy);
        ((__nv_bfloat162*)dh)[1] = __nv_bfloat162(hz, hw);
        ((__nv_bfloat162*)dl)[0] = __nv_bfloat162(lx, ly);
        ((__nv_bfloat162*)dl)[1] = __nv_bfloat162(lz, lw);
    }
}

__global__ __launch_bounds__(256) void convert_gA() {
    const int total4 = MROWS * DIM / 4;
    for (int i = blockIdx.x * blockDim.x + threadIdx.x; i < total4;
         i += gridDim.x * blockDim.x) {
        int e = i * 4;
        float4 v = *(const float4*)(g_A + e);
        __nv_bfloat16 hx, lx, hy, ly, hz, lz, hw, lw;
        bf16_split(v.x, hx, lx);
        bf16_split(v.y, hy, ly);
        bf16_split(v.z, hz, lz);
        bf16_split(v.w, hw, lw);
        ((__nv_bfloat162*)(gAhi + e))[0] = __nv_bfloat162(hx, hy);
        ((__nv_bfloat162*)(gAhi + e))[1] = __nv_bfloat162(hz, hw);
        ((__nv_bfloat162*)(gAlo + e))[0] = __nv_bfloat162(lx, ly);
        ((__nv_bfloat162*)(gAlo + e))[1] = __nv_bfloat162(lz, lw);
    }
}

// ---------------------------------------------------------------------------
// Tensor-core GEMM via mma.sync bf16, fp32-accurate with hi/lo split:
//   C = Ahi*Bhi + Ahi*Blo + Alo*Bhi
// CTA tile 128x128, K-step 32, 8 warps (2m x 4n), 2-stage cp.async pipeline.
// smem per stage (32 KB):
//   A  [128 rows][128B]: chunks 0-3 = hi k0..31, 4-7 = lo k0..31, XOR swizzle
//   Bhi[32 k][256B], Blo[32 k][256B]: 16 chunks/row, XOR swizzle per 128B half
// ---------------------------------------------------------------------------
#define STAGE_BYTES 32768
#define SM_BHI 16384
#define SM_BLO 24576
#define GEMM_SMEM (2 * STAGE_BYTES)

__device__ __forceinline__ void gemm_fill(uint32_t sbuf,
                                          const __nv_bfloat16* __restrict__ Ahi,
                                          const __nv_bfloat16* __restrict__ Alo,
                                          const __nv_bfloat16* __restrict__ Bhi,
                                          const __nv_bfloat16* __restrict__ Blo,
                                          int row0, int col0, int kt, int tid) {
#pragma unroll
    for (int i = 0; i < 4; ++i) {  // A: 1024 16B chunks
        int lin = tid + i * 256;
        int m = lin >> 3, c = lin & 7;
        const __nv_bfloat16* src =
            ((c < 4) ? Ahi : Alo) + (size_t)(row0 + m) * DIM + kt + (c & 3) * 8;
        uint32_t dst = sbuf + m * 128 + ((c ^ (m & 7)) << 4);
        cp16(dst, src);
    }
#pragma unroll
    for (int i = 0; i < 4; ++i) {  // B: 1024 16B chunks (512 hi + 512 lo)
        int lin = tid + i * 256;
        int tile = lin >> 9, rem = lin & 511;
        int k = rem >> 4, c = rem & 15;
        const __nv_bfloat16* src =
            (tile ? Blo : Bhi) + (size_t)(kt + k) * DIM + col0 + c * 8;
        uint32_t dst = sbuf + (tile ? SM_BLO : SM_BHI) + k * 256 +
                       ((c >> 3) << 7) + (((c & 7) ^ (k & 7)) << 4);
        cp16(dst, src);
    }
}

__device__ __forceinline__ void mma_gemm_body(
    const __nv_bfloat16* __restrict__ Ahi_g, const __nv_bfloat16* __restrict__ Alo_g,
    const __nv_bfloat16* __restrict__ Bhi_g, const __nv_bfloat16* __restrict__ Blo_g,
    const float* __restrict__ bias, float* __restrict__ Y) {
    extern __shared__ __align__(1024) char smem[];
    const uint32_t sb = smem_u32(smem);
    const int tid = threadIdx.x;
    const int row0 = blockIdx.y * 128, col0 = blockIdx.x * 128;
    const int lane = tid & 31, wid = tid >> 5;
    const int wm = wid & 1, wn = wid >> 1;
    const int q = lane >> 3, r = lane & 7;
    const int arow = (q & 1) * 8 + r;  // row within 16
    const int aq = q >> 1;             // 16B half of k16

    float acc[4][4][4];
#pragma unroll
    for (int mt = 0; mt < 4; ++mt)
#pragma unroll
        for (int nt = 0; nt < 4; ++nt)
#pragma unroll
            for (int e = 0; e < 4; ++e) acc[mt][nt][e] = 0.f;

    gemm_fill(sb, Ahi_g, Alo_g, Bhi_g, Blo_g, row0, col0, 0, tid);
    cp_commit();

    int buf = 0;
    for (int s = 0; s < 32; ++s) {
        if (s + 1 < 32) {
            gemm_fill(sb + (buf ^ 1) * STAGE_BYTES, Ahi_g, Alo_g, Bhi_g, Blo_g,
                      row0, col0, (s + 1) * 32, tid);
            cp_commit();
            asm volatile("cp.async.wait_group 1;" ::: "memory");
        } else {
            asm volatile("cp.async.wait_group 0;" ::: "memory");
        }
        __syncthreads();

        const uint32_t sA = sb + buf * STAGE_BYTES;
        const uint32_t sBh = sA + SM_BHI;
        const uint32_t sBl = sA + SM_BLO;

#pragma unroll
        for (int k16 = 0; k16 < 2; ++k16) {
            uint32_t bh[8], bl[8];
            {
                const int krow = k16 * 16 + (q & 1) * 8 + r;
#pragma unroll
                for (int g2 = 0; g2 < 2; ++g2) {  // two n16 groups
                    int cg = wn * 4 + g2 * 2 + (q >> 1);
                    uint32_t baddr = krow * 256 + ((cg >> 3) << 7) +
                                     (((cg & 7) ^ (krow & 7)) << 4);
                    ldsm4t(&bh[g2 * 4], sBh + baddr);
                    ldsm4t(&bl[g2 * 4], sBl + baddr);
                }
            }
            uint32_t a[4][4];
#pragma unroll
            for (int mt = 0; mt < 4; ++mt) {  // A hi
                int row = wm * 64 + mt * 16 + arow;
                int c = k16 * 2 + aq;
                ldsm4(a[mt], sA + row * 128 + ((c ^ r) << 4));
            }
#pragma unroll
            for (int mt = 0; mt < 4; ++mt)
#pragma unroll
                for (int nt = 0; nt < 4; ++nt)
                    mma16816(acc[mt][nt], a[mt], &bh[(nt >> 1) * 4 + (nt & 1) * 2]);
#pragma unroll
            for (int mt = 0; mt < 4; ++mt)
#pragma unroll
                for (int nt = 0; nt < 4; ++nt)
                    mma16816(acc[mt][nt], a[mt], &bl[(nt >> 1) * 4 + (nt & 1) * 2]);
#pragma unroll
            for (int mt = 0; mt < 4; ++mt) {  // A lo
                int row = wm * 64 + mt * 16 + arow;
                int c = 4 + k16 * 2 + aq;
                ldsm4(a[mt], sA + row * 128 + ((c ^ r) << 4));
            }
#pragma unroll
            for (int mt = 0; mt < 4; ++mt)
#pragma unroll
                for (int nt = 0; nt < 4; ++nt)
                    mma16816(acc[mt][nt], a[mt], &bh[(nt >> 1) * 4 + (nt & 1) * 2]);
        }
        __syncthreads();
        buf ^= 1;
    }

    // epilogue: m16n8 C layout: c0:(g,2t) c1:(g,2t+1) c2:(g+8,2t) c3:(g+8,2t+1)
    const int cg = lane >> 2, ct = lane & 3;
#pragma unroll
    for (int mt = 0; mt < 4; ++mt) {
        int r0 = row0 + wm * 64 + mt * 16 + cg;
#pragma unroll
        for (int nt = 0; nt < 4; ++nt) {
            int col = col0 + wn * 32 + nt * 8 + ct * 2;
            float b0 = bias ? bias[col] : 0.f;
            float b1 = bias ? bias[col + 1] : 0.f;
            float2 v0 = make_float2(acc[mt][nt][0] + b0, acc[mt][nt][1] + b1);
            float2 v1 = make_float2(acc[mt][nt][2] + b0, acc[mt][nt][3] + b1);
            *(float2*)(Y + (size_t)r0 * DIM + col) = v0;
            *(float2*)(Y + (size_t)(r0 + 8) * DIM + col) = v1;
        }
    }
}

__global__ __launch_bounds__(256, 2) void qkv_mma(const float* __restrict__ bq,
                                                  const float* __restrict__ bk) {
    const int z = blockIdx.z;
    const __nv_bfloat16* Bh = gWhi + (size_t)z * DIM * DIM;
    const __nv_bfloat16* Bl = gWlo + (size_t)z * DIM * DIM;
    const float* bias = (z == 0) ? bq : (z == 1) ? bk : nullptr;
    float* Y = (z == 0) ? g_Q : (z == 1) ? g_K : g_V;
    mma_gemm_body(gXhi, gXlo, Bh, Bl, bias, Y);
}

__global__ __launch_bounds__(256, 2) void out_mma(const float* __restrict__ bo,
                                                  float* __restrict__ out) {
    mma_gemm_body(gAhi, gAlo, gWhi + (size_t)3 * DIM * DIM,
                  gWlo + (size_t)3 * DIM * DIM, bo, out);
}

// ---------------------------------------------------------------------------
// Flash attention, causal + ALiBi-style key bias (fp32 SIMT, known-good R1).
// Stochastic soft mask (mean -1e9, std 1e8) underflows exp() to 0 -> hard mask.
// ---------------------------------------------------------------------------
struct AttnSmem {
    float Qt[64][128];
    float Kt[64][128];
    float Vs[128][64];
    float Ps[128][132];
};

__global__ __launch_bounds__(256, 1) void attn_kernel() {
    extern __shared__ __align__(1024) char smraw2[];
    AttnSmem& sm = *reinterpret_cast<AttnSmem*>(smraw2);

    const int tid = threadIdx.x;
    const int tx = tid & 15;
    const int ty = tid >> 4;
    const int it = 15 - (int)blockIdx.x;
    const int bh = blockIdx.y;
    const int b = bh >> 4;
    const int h = bh & 15;
    const int i0 = it * 128;
    const float slope = exp2f(-0.5f * (float)(h + 1));

    const size_t base = (size_t)(b * SEQ) * DIM + (size_t)h * HDIM;
    const float* Qg = g_Q + base + (size_t)i0 * DIM;

    for (int idx = tid; idx < 128 * 16; idx += 256) {
        int rr = idx >> 4;
        int c4 = (idx & 15) << 2;
        float4 v = *(const float4*)(Qg + (size_t)rr * DIM + c4);
        int sw = (c4 >> 2) & 7;
        int col = ((((rr >> 2) ^ sw) << 2) | (rr & 3));
        sm.Qt[c4 + 0][col] = v.x;
        sm.Qt[c4 + 1][col] = v.y;
        sm.Qt[c4 + 2][col] = v.z;
        sm.Qt[c4 + 3][col] = v.w;
    }

    float m[8], l[8], acc[8][4];
#pragma unroll
    for (int a = 0; a < 8; a++) {
        m[a] = -1e30f;
        l[a] = 0.f;
        acc[a][0] = acc[a][1] = acc[a][2] = acc[a][3] = 0.f;
    }

    const int ibase = 8 * ty;

    for (int jt = 0; jt <= it; jt++) {
        const int j0 = jt * 128;
        const float* Kg = g_K + base + (size_t)j0 * DIM;
        const float* Vg = g_V + base + (size_t)j0 * DIM;

        __syncthreads();
        for (int idx = tid; idx < 128 * 16; idx += 256) {
            int rr = idx >> 4;
            int c4 = (idx & 15) << 2;
            float4 kv = *(const float4*)(Kg + (size_t)rr * DIM + c4);
            int sw = (c4 >> 2) & 7;
            int col = ((((rr >> 2) ^ sw) << 2) | (rr & 3));
            sm.Kt[c4 + 0][col] = kv.x;
            sm.Kt[c4 + 1][col] = kv.y;
            sm.Kt[c4 + 2][col] = kv.z;
            sm.Kt[c4 + 3][col] = kv.w;
            float4 vv = *(const float4*)(Vg + (size_t)rr * DIM + c4);
            *(float4*)&sm.Vs[rr][c4] = vv;
        }
        __syncthreads();

        float s[8][8];
#pragma unroll
        for (int a = 0; a < 8; a++)
#pragma unroll
            for (int bb = 0; bb < 8; bb++) s[a][bb] = 0.f;

#pragma unroll 8
        for (int d = 0; d < 64; d++) {
            const int sw = (d >> 2) & 7;
            const float* qrow = sm.Qt[d];
            const float* krow = sm.Kt[d];
            float4 q0 = *(const float4*)(qrow + (((2 * ty) ^ sw) << 2));
            float4 q1 = *(const float4*)(qrow + (((2 * ty + 1) ^ sw) << 2));
            float4 k0 = *(const float4*)(krow + ((tx ^ sw) << 2));
            float4 k1 = *(const float4*)(krow + (((tx + 16) ^ sw) << 2));
            float qa[8] = {q0.x, q0.y, q0.z, q0.w, q1.x, q1.y, q1.z, q1.w};
            float kb[8] = {k0.x, k0.y, k0.z, k0.w, k1.x, k1.y, k1.z, k1.w};
#pragma unroll
            for (int a = 0; a < 8; a++)
#pragma unroll
                for (int bb = 0; bb < 8; bb++)
                    s[a][bb] = fmaf(qa[a], kb[bb], s[a][bb]);
        }

        const bool diag = (jt == it);
#pragma unroll
        for (int a = 0; a < 8; a++) {
            const int il = ibase + a;
            float rm = -1e30f;
#pragma unroll
            for (int bb = 0; bb < 8; bb++) {
                int jl = 4 * tx + (bb & 3) + ((bb >> 2) << 6);
                float v = s[a][bb] * 0.125f - slope * (float)(j0 + jl);
                if (diag && jl > il) v = -1e30f;
                s[a][bb] = v;
                rm = fmaxf(rm, v);
            }
#pragma unroll
            for (int o = 8; o > 0; o >>= 1)
                rm = fmaxf(rm, __shfl_xor_sync(0xffffffffu, rm, o, 16));
            float mn = fmaxf(m[a], rm);
            float corr = __expf(m[a] - mn);
            m[a] = mn;
            float rs = 0.f;
#pragma unroll
            for (int bb = 0; bb < 8; bb++) {
                float p = __expf(s[a][bb] - mn);
                s[a][bb] = p;
                rs += p;
            }
#pragma unroll
            for (int o = 8; o > 0; o >>= 1)
                rs += __shfl_xor_sync(0xffffffffu, rs, o, 16);
            l[a] = l[a] * corr + rs;
            acc[a][0] *= corr;
            acc[a][1] *= corr;
            acc[a][2] *= corr;
            acc[a][3] *= corr;
        }

#pragma unroll
        for (int a = 0; a < 8; a++) {
            *(float4*)&sm.Ps[ibase + a][4 * tx] =
                make_float4(s[a][0], s[a][1], s[a][2], s[a][3]);
            *(float4*)&sm.Ps[ibase + a][64 + 4 * tx] =
                make_float4(s[a][4], s[a][5], s[a][6], s[a][7]);
        }
        __syncthreads();

#pragma unroll 4
        for (int j4 = 0; j4 < 32; j4++) {
            float4 v0 = *(const float4*)&sm.Vs[4 * j4 + 0][4 * tx];
            float4 v1 = *(const float4*)&sm.Vs[4 * j4 + 1][4 * tx];
            float4 v2 = *(const float4*)&sm.Vs[4 * j4 + 2][4 * tx];
            float4 v3 = *(const float4*)&sm.Vs[4 * j4 + 3][4 * tx];
#pragma unroll
            for (int a = 0; a < 8; a++) {
                float4 p = *(const float4*)&sm.Ps[ibase + a][4 * j4];
                acc[a][0] = fmaf(p.x, v0.x, fmaf(p.y, v1.x, fmaf(p.z, v2.x, fmaf(p.w, v3.x, acc[a][0]))));
                acc[a][1] = fmaf(p.x, v0.y, fmaf(p.y, v1.y, fmaf(p.z, v2.y, fmaf(p.w, v3.y, acc[a][1]))));
                acc[a][2] = fmaf(p.x, v0.z, fmaf(p.y, v1.z, fmaf(p.z, v2.z, fmaf(p.w, v3.z, acc[a][2]))));
                acc[a][3] = fmaf(p.x, v0.w, fmaf(p.y, v1.w, fmaf(p.z, v2.w, fmaf(p.w, v3.w, acc[a][3]))));
            }
        }
    }

    float* Og = g_A + base + (size_t)i0 * DIM;
#pragma unroll
    for (int a = 0; a < 8; a++) {
        float inv = 1.0f / l[a];
        float4 o = make_float4(acc[a][0] * inv, acc[a][1] * inv,
                               acc[a][2] * inv, acc[a][3] * inv);
        *(float4*)(Og + (size_t)(ibase + a) * DIM + 4 * tx) = o;
    }
}

// ---------------------------------------------------------------------------
extern "C" void kernel_launch(void* const* d_in, const int* in_sizes, int n_in,
                              void* d_out, int out_size) {
    const float* X  = (const float*)d_in[0];
    const float* Wq = (const float*)d_in[1];
    const float* bq = (const float*)d_in[2];
    const float* Wk = (const float*)d_in[3];
    const float* bk = (const float*)d_in[4];
    const float* Wv = (const float*)d_in[5];
    const float* Wo = (const float*)d_in[6];
    const float* bo = (const float*)d_in[7];
    float* out = (float*)d_out;

    cudaFuncSetAttribute(qkv_mma, cudaFuncAttributeMaxDynamicSharedMemorySize, GEMM_SMEM);
    cudaFuncSetAttribute(out_mma, cudaFuncAttributeMaxDynamicSharedMemorySize, GEMM_SMEM);
    cudaFuncSetAttribute(attn_kernel, cudaFuncAttributeMaxDynamicSharedMemorySize,
                         (int)sizeof(AttnSmem));

    convert_inputs<<<2048, 256>>>(X, Wq, Wk, Wv, Wo);
    qkv_mma<<<dim3(DIM / 128, MROWS / 128, 3), 256, GEMM_SMEM>>>(bq, bk);
    attn_kernel<<<dim3(SEQ / 128, BQ * NH), 256, sizeof(AttnSmem)>>>();
    convert_gA<<<1024, 256>>>();
    out_mma<<<dim3(DIM / 128, MROWS / 128, 1), 256, GEMM_SMEM>>>(bo, out);
}

// round 4
// speedup vs baseline: 2.8740x; 1.7467x over previous
#include <cuda_runtime.h>
#include <cuda_bf16.h>
#include <math.h>
#include <stdint.h>

// Problem constants
#define BQ   2
#define SEQ  2048
#define DIM  1024
#define NH   16
#define HDIM 64
#define MROWS (BQ * SEQ)   // 4096

// Scratch (device globals: allocation-free). All bf16 hi/lo pairs.
__device__ __nv_bfloat16 gXh[MROWS * DIM];
__device__ __nv_bfloat16 gXl[MROWS * DIM];
__device__ __nv_bfloat16 gWh[4 * DIM * DIM];
__device__ __nv_bfloat16 gWl[4 * DIM * DIM];
__device__ __nv_bfloat16 gQh[MROWS * DIM];
__device__ __nv_bfloat16 gQl[MROWS * DIM];
__device__ __nv_bfloat16 gKh[MROWS * DIM];
__device__ __nv_bfloat16 gKl[MROWS * DIM];
__device__ __nv_bfloat16 gVh[MROWS * DIM];
__device__ __nv_bfloat16 gVl[MROWS * DIM];
__device__ __nv_bfloat16 gOh[MROWS * DIM];
__device__ __nv_bfloat16 gOl[MROWS * DIM];

// ---------------------------------------------------------------------------
// Helpers
// ---------------------------------------------------------------------------
__device__ __forceinline__ uint32_t smem_u32(const void* p) {
    uint32_t a;
    asm("{ .reg .u64 t; cvta.to.shared.u64 t, %1; cvt.u32.u64 %0, t; }"
        : "=r"(a) : "l"(p));
    return a;
}
__device__ __forceinline__ void cp16(uint32_t dst, const void* src) {
    asm volatile("cp.async.cg.shared.global [%0], [%1], 16;"
                 :: "r"(dst), "l"(__cvta_generic_to_global(src)));
}
__device__ __forceinline__ void cp_commit() {
    asm volatile("cp.async.commit_group;" ::: "memory");
}
__device__ __forceinline__ void ldsm4(uint32_t* r, uint32_t addr) {
    asm volatile("ldmatrix.sync.aligned.m8n8.x4.shared.b16 {%0,%1,%2,%3}, [%4];"
                 : "=r"(r[0]), "=r"(r[1]), "=r"(r[2]), "=r"(r[3]) : "r"(addr));
}
__device__ __forceinline__ void ldsm4t(uint32_t* r, uint32_t addr) {
    asm volatile("ldmatrix.sync.aligned.m8n8.x4.trans.shared.b16 {%0,%1,%2,%3}, [%4];"
                 : "=r"(r[0]), "=r"(r[1]), "=r"(r[2]), "=r"(r[3]) : "r"(addr));
}
__device__ __forceinline__ void mma16816(float* c, const uint32_t* a, const uint32_t* b) {
    asm volatile(
        "mma.sync.aligned.m16n8k16.row.col.f32.bf16.bf16.f32 "
        "{%0,%1,%2,%3}, {%4,%5,%6,%7}, {%8,%9}, {%0,%1,%2,%3};"
        : "+f"(c[0]), "+f"(c[1]), "+f"(c[2]), "+f"(c[3])
        : "r"(a[0]), "r"(a[1]), "r"(a[2]), "r"(a[3]), "r"(b[0]), "r"(b[1]));
}
__device__ __forceinline__ uint32_t pack_bf2(__nv_bfloat16 a, __nv_bfloat16 b) {
    __nv_bfloat162 t(a, b);
    return *(uint32_t*)&t;
}
__device__ __forceinline__ void pack_hilo(float f0, float f1, uint32_t& hi, uint32_t& lo) {
    __nv_bfloat16 h0 = __float2bfloat16_rn(f0);
    __nv_bfloat16 h1 = __float2bfloat16_rn(f1);
    __nv_bfloat16 e0 = __float2bfloat16_rn(f0 - __bfloat162float(h0));
    __nv_bfloat16 e1 = __float2bfloat16_rn(f1 - __bfloat162float(h1));
    hi = pack_bf2(h0, h1);
    lo = pack_bf2(e0, e1);
}
__device__ __forceinline__ void bf16_split(float x, __nv_bfloat16& hi, __nv_bfloat16& lo) {
    hi = __float2bfloat16_rn(x);
    lo = __float2bfloat16_rn(x - __bfloat162float(hi));
}

// ---------------------------------------------------------------------------
// Convert fp32 inputs -> bf16 hi/lo pairs (X and the 4 weight matrices)
// ---------------------------------------------------------------------------
__global__ __launch_bounds__(256) void convert_inputs(
    const float* __restrict__ X, const float* __restrict__ Wq,
    const float* __restrict__ Wk, const float* __restrict__ Wv,
    const float* __restrict__ Wo) {
    const int XQ = MROWS * DIM / 4;
    const int WQ = DIM * DIM / 4;
    const int total4 = XQ + 4 * WQ;
    for (int i = blockIdx.x * blockDim.x + threadIdx.x; i < total4;
         i += gridDim.x * blockDim.x) {
        const float* src;
        __nv_bfloat16 *dh, *dl;
        if (i < XQ) {
            int e = i * 4;
            src = X + e; dh = gXh + e; dl = gXl + e;
        } else {
            int t = i - XQ;
            int w = t / WQ;
            int off = (t - w * WQ) * 4;
            src = (w == 0) ? Wq + off : (w == 1) ? Wk + off
                  : (w == 2) ? Wv + off : Wo + off;
            dh = gWh + (size_t)w * DIM * DIM + off;
            dl = gWl + (size_t)w * DIM * DIM + off;
        }
        float4 v = *(const float4*)src;
        __nv_bfloat16 hx, lx, hy, ly, hz, lz, hw, lw;
        bf16_split(v.x, hx, lx);
        bf16_split(v.y, hy, ly);
        bf16_split(v.z, hz, lz);
        bf16_split(v.w, hw, lw);
        ((__nv_bfloat162*)dh)[0] = __nv_bfloat162(hx, hy);
        ((__nv_bfloat162*)dh)[1] = __nv_bfloat162(hz, hw);
        ((__nv_bfloat162*)dl)[0] = __nv_bfloat162(lx, ly);
        ((__nv_bfloat162*)dl)[1] = __nv_bfloat162(lz, lw);
    }
}

// ---------------------------------------------------------------------------
// Tensor-core GEMM (hi/lo bf16, 3-MMA): 128x128 CTA tile, K-step 32,
// 8 warps (2m x 4n), 2-stage cp.async. Epilogue writes either fp32 (final
// output) or bf16 hi/lo pairs (intermediate tensors).
// ---------------------------------------------------------------------------
#define STAGE_BYTES 32768
#define SM_BHI 16384
#define SM_BLO 24576
#define GEMM_SMEM (2 * STAGE_BYTES)

__device__ __forceinline__ void gemm_fill(uint32_t sbuf,
                                          const __nv_bfloat16* __restrict__ Ahi,
                                          const __nv_bfloat16* __restrict__ Alo,
                                          const __nv_bfloat16* __restrict__ Bhi,
                                          const __nv_bfloat16* __restrict__ Blo,
                                          int row0, int col0, int kt, int tid) {
#pragma unroll
    for (int i = 0; i < 4; ++i) {
        int lin = tid + i * 256;
        int m = lin >> 3, c = lin & 7;
        const __nv_bfloat16* src =
            ((c < 4) ? Ahi : Alo) + (size_t)(row0 + m) * DIM + kt + (c & 3) * 8;
        uint32_t dst = sbuf + m * 128 + ((c ^ (m & 7)) << 4);
        cp16(dst, src);
    }
#pragma unroll
    for (int i = 0; i < 4; ++i) {
        int lin = tid + i * 256;
        int tile = lin >> 9, rem = lin & 511;
        int k = rem >> 4, c = rem & 15;
        const __nv_bfloat16* src =
            (tile ? Blo : Bhi) + (size_t)(kt + k) * DIM + col0 + c * 8;
        uint32_t dst = sbuf + (tile ? SM_BLO : SM_BHI) + k * 256 +
                       ((c >> 3) << 7) + (((c & 7) ^ (k & 7)) << 4);
        cp16(dst, src);
    }
}

__device__ __forceinline__ void mma_gemm_body(
    const __nv_bfloat16* __restrict__ Ahi_g, const __nv_bfloat16* __restrict__ Alo_g,
    const __nv_bfloat16* __restrict__ Bhi_g, const __nv_bfloat16* __restrict__ Blo_g,
    const float* __restrict__ bias, float* __restrict__ Yf,
    __nv_bfloat16* __restrict__ Yhi, __nv_bfloat16* __restrict__ Ylo) {
    extern __shared__ __align__(1024) char smem[];
    const uint32_t sb = smem_u32(smem);
    const int tid = threadIdx.x;
    const int row0 = blockIdx.y * 128, col0 = blockIdx.x * 128;
    const int lane = tid & 31, wid = tid >> 5;
    const int wm = wid & 1, wn = wid >> 1;
    const int q = lane >> 3, r = lane & 7;
    const int arow = (q & 1) * 8 + r;
    const int aq = q >> 1;

    float acc[4][4][4];
#pragma unroll
    for (int mt = 0; mt < 4; ++mt)
#pragma unroll
        for (int nt = 0; nt < 4; ++nt)
#pragma unroll
            for (int e = 0; e < 4; ++e) acc[mt][nt][e] = 0.f;

    gemm_fill(sb, Ahi_g, Alo_g, Bhi_g, Blo_g, row0, col0, 0, tid);
    cp_commit();

    int buf = 0;
    for (int s = 0; s < 32; ++s) {
        if (s + 1 < 32) {
            gemm_fill(sb + (buf ^ 1) * STAGE_BYTES, Ahi_g, Alo_g, Bhi_g, Blo_g,
                      row0, col0, (s + 1) * 32, tid);
            cp_commit();
            asm volatile("cp.async.wait_group 1;" ::: "memory");
        } else {
            asm volatile("cp.async.wait_group 0;" ::: "memory");
        }
        __syncthreads();

        const uint32_t sA = sb + buf * STAGE_BYTES;
        const uint32_t sBh = sA + SM_BHI;
        const uint32_t sBl = sA + SM_BLO;

#pragma unroll
        for (int k16 = 0; k16 < 2; ++k16) {
            uint32_t bh[8], bl[8];
            {
                const int krow = k16 * 16 + (q & 1) * 8 + r;
#pragma unroll
                for (int g2 = 0; g2 < 2; ++g2) {
                    int cg = wn * 4 + g2 * 2 + (q >> 1);
                    uint32_t baddr = krow * 256 + ((cg >> 3) << 7) +
                                     (((cg & 7) ^ (krow & 7)) << 4);
                    ldsm4t(&bh[g2 * 4], sBh + baddr);
                    ldsm4t(&bl[g2 * 4], sBl + baddr);
                }
            }
            uint32_t a[4][4];
#pragma unroll
            for (int mt = 0; mt < 4; ++mt) {
                int row = wm * 64 + mt * 16 + arow;
                int c = k16 * 2 + aq;
                ldsm4(a[mt], sA + row * 128 + ((c ^ r) << 4));
            }
#pragma unroll
            for (int mt = 0; mt < 4; ++mt)
#pragma unroll
                for (int nt = 0; nt < 4; ++nt)
                    mma16816(acc[mt][nt], a[mt], &bh[(nt >> 1) * 4 + (nt & 1) * 2]);
#pragma unroll
            for (int mt = 0; mt < 4; ++mt)
#pragma unroll
                for (int nt = 0; nt < 4; ++nt)
                    mma16816(acc[mt][nt], a[mt], &bl[(nt >> 1) * 4 + (nt & 1) * 2]);
#pragma unroll
            for (int mt = 0; mt < 4; ++mt) {
                int row = wm * 64 + mt * 16 + arow;
                int c = 4 + k16 * 2 + aq;
                ldsm4(a[mt], sA + row * 128 + ((c ^ r) << 4));
            }
#pragma unroll
            for (int mt = 0; mt < 4; ++mt)
#pragma unroll
                for (int nt = 0; nt < 4; ++nt)
                    mma16816(acc[mt][nt], a[mt], &bh[(nt >> 1) * 4 + (nt & 1) * 2]);
        }
        __syncthreads();
        buf ^= 1;
    }

    const int cg = lane >> 2, ct = lane & 3;
#pragma unroll
    for (int mt = 0; mt < 4; ++mt) {
        int r0 = row0 + wm * 64 + mt * 16 + cg;
#pragma unroll
        for (int nt = 0; nt < 4; ++nt) {
            int col = col0 + wn * 32 + nt * 8 + ct * 2;
            float b0 = bias ? bias[col] : 0.f;
            float b1 = bias ? bias[col + 1] : 0.f;
            float v00 = acc[mt][nt][0] + b0, v01 = acc[mt][nt][1] + b1;
            float v10 = acc[mt][nt][2] + b0, v11 = acc[mt][nt][3] + b1;
            if (Yf) {
                *(float2*)(Yf + (size_t)r0 * DIM + col) = make_float2(v00, v01);
                *(float2*)(Yf + (size_t)(r0 + 8) * DIM + col) = make_float2(v10, v11);
            } else {
                uint32_t hi, lo;
                pack_hilo(v00, v01, hi, lo);
                *(uint32_t*)&Yhi[(size_t)r0 * DIM + col] = hi;
                *(uint32_t*)&Ylo[(size_t)r0 * DIM + col] = lo;
                pack_hilo(v10, v11, hi, lo);
                *(uint32_t*)&Yhi[(size_t)(r0 + 8) * DIM + col] = hi;
                *(uint32_t*)&Ylo[(size_t)(r0 + 8) * DIM + col] = lo;
            }
        }
    }
}

__global__ __launch_bounds__(256, 2) void qkv_mma(const float* __restrict__ bq,
                                                  const float* __restrict__ bk) {
    const int z = blockIdx.z;
    const __nv_bfloat16* Bh = gWh + (size_t)z * DIM * DIM;
    const __nv_bfloat16* Bl = gWl + (size_t)z * DIM * DIM;
    const float* bias = (z == 0) ? bq : (z == 1) ? bk : nullptr;
    __nv_bfloat16* Yh = (z == 0) ? gQh : (z == 1) ? gKh : gVh;
    __nv_bfloat16* Yl = (z == 0) ? gQl : (z == 1) ? gKl : gVl;
    mma_gemm_body(gXh, gXl, Bh, Bl, bias, nullptr, Yh, Yl);
}

__global__ __launch_bounds__(256, 2) void out_mma(const float* __restrict__ bo,
                                                  float* __restrict__ out) {
    mma_gemm_body(gOh, gOl, gWh + (size_t)3 * DIM * DIM,
                  gWl + (size_t)3 * DIM * DIM, bo, out, nullptr, nullptr);
}

// ---------------------------------------------------------------------------
// Flash attention on tensor cores. 256 threads = 8 warps; warp w owns query
// rows w*16..w*16+15 of a 128-row i-tile, full 128-key j-tiles.
// Stochastic soft mask (mean -1e9, std 1e8) underflows exp() -> hard causal.
// smem: Qh/Ql [128][64] + 2 stages of {Kh,Kl,Vh,Vl}[128][64].
// ---------------------------------------------------------------------------
#define A_SQ 0
#define A_ST0 32768
#define A_STAGE 65536
#define ATTN_SMEM (32768 + 2 * 65536)

__global__ __launch_bounds__(256, 1) void attn_mma() {
    extern __shared__ __align__(1024) char smem[];
    const uint32_t sb = smem_u32(smem);
    const int tid = threadIdx.x;
    const int lane = tid & 31, w = tid >> 5;
    const int q = lane >> 3, r = lane & 7;
    const int g = lane >> 2, t = lane & 3;
    const int it = 15 - (int)blockIdx.x;  // heavy tiles first
    const int bh = blockIdx.y;
    const int b = bh >> 4, h = bh & 15;
    const int i0 = it * 128;
    const float slope = exp2f(-0.5f * (float)(h + 1));
    const int qrow_base = b * SEQ + i0;   // global row in [4096] space
    const int hcol = h * HDIM;

    // ---- fill Q (hi+lo) ----
#pragma unroll
    for (int i = 0; i < 8; ++i) {
        int lin = tid + i * 256;
        int tz = lin >> 10;         // 0=hi 1=lo
        int rem = lin & 1023;
        int m = rem >> 3, c = rem & 7;
        const __nv_bfloat16* src =
            (tz ? gQl : gQh) + (size_t)(qrow_base + m) * DIM + hcol + c * 8;
        cp16(sb + tz * 16384 + m * 128 + ((c ^ (m & 7)) << 4), src);
    }
    // ---- fill K/V stage 0 (j0 = 0) ----
    {
        const int krow_base = b * SEQ;
#pragma unroll
        for (int i = 0; i < 16; ++i) {
            int lin = tid + i * 256;
            int tz = lin >> 10;     // 0=Kh 1=Kl 2=Vh 3=Vl
            int rem = lin & 1023;
            int m = rem >> 3, c = rem & 7;
            const __nv_bfloat16* src =
                ((tz == 0) ? gKh : (tz == 1) ? gKl : (tz == 2) ? gVh : gVl) +
                (size_t)(krow_base + m) * DIM + hcol + c * 8;
            cp16(sb + A_ST0 + tz * 16384 + m * 128 + ((c ^ (m & 7)) << 4), src);
        }
    }
    cp_commit();

    float o[8][4];
#pragma unroll
    for (int nt = 0; nt < 8; ++nt)
#pragma unroll
        for (int e = 0; e < 4; ++e) o[nt][e] = 0.f;
    float m0 = -1e30f, m1 = -1e30f, l0 = 0.f, l1 = 0.f;
    uint32_t qh[4][4], ql[4][4];

    int buf = 0;
    for (int jt = 0; jt <= it; ++jt) {
        if (jt < it) {
            const int krow_base = b * SEQ + (jt + 1) * 128;
            const uint32_t st = sb + A_ST0 + (buf ^ 1) * A_STAGE;
#pragma unroll
            for (int i = 0; i < 16; ++i) {
                int lin = tid + i * 256;
                int tz = lin >> 10;
                int rem = lin & 1023;
                int m = rem >> 3, c = rem & 7;
                const __nv_bfloat16* src =
                    ((tz == 0) ? gKh : (tz == 1) ? gKl : (tz == 2) ? gVh : gVl) +
                    (size_t)(krow_base + m) * DIM + hcol + c * 8;
                cp16(st + tz * 16384 + m * 128 + ((c ^ (m & 7)) << 4), src);
            }
            cp_commit();
            asm volatile("cp.async.wait_group 1;" ::: "memory");
        } else {
            asm volatile("cp.async.wait_group 0;" ::: "memory");
        }
        __syncthreads();

        if (jt == 0) {  // hoist Q fragments into registers
#pragma unroll
            for (int k16 = 0; k16 < 4; ++k16) {
                int row = w * 16 + (q & 1) * 8 + r;
                int c = k16 * 2 + (q >> 1);
                uint32_t ad = sb + row * 128 + ((c ^ r) << 4);
                ldsm4(qh[k16], ad);
                ldsm4(ql[k16], ad + 16384);
            }
        }

        const uint32_t sk = sb + A_ST0 + buf * A_STAGE;
        const uint32_t sv = sk + 32768;

        // ---- S = Q K^T (3-term hi/lo) ----
        float s[16][4];
#pragma unroll
        for (int nt = 0; nt < 16; ++nt)
#pragma unroll
            for (int e = 0; e < 4; ++e) s[nt][e] = 0.f;

#pragma unroll
        for (int nt16 = 0; nt16 < 8; ++nt16) {
            const int row = nt16 * 16 + (q >> 1) * 8 + r;
#pragma unroll
            for (int k16 = 0; k16 < 4; ++k16) {
                const int c = k16 * 2 + (q & 1);
                uint32_t ad = sk + row * 128 + ((c ^ r) << 4);
                uint32_t kh[4], kl[4];
                ldsm4(kh, ad);
                ldsm4(kl, ad + 16384);
                mma16816(s[2 * nt16], qh[k16], kh);
                mma16816(s[2 * nt16], qh[k16], kl);
                mma16816(s[2 * nt16], ql[k16], kh);
                mma16816(s[2 * nt16 + 1], qh[k16], kh + 2);
                mma16816(s[2 * nt16 + 1], qh[k16], kl + 2);
                mma16816(s[2 * nt16 + 1], ql[k16], kh + 2);
            }
        }

        // ---- online softmax ----
        const int j0 = jt * 128;
        const int rowg0 = i0 + w * 16 + g;
        const int rowg1 = rowg0 + 8;
        const bool diag = (jt == it);
        float mx0 = -1e30f, mx1 = -1e30f;
#pragma unroll
        for (int nt = 0; nt < 16; ++nt) {
            const int jc = j0 + nt * 8 + 2 * t;
            const float c0 = (float)jc;
            s[nt][0] = s[nt][0] * 0.125f - slope * c0;
            s[nt][1] = s[nt][1] * 0.125f - slope * (c0 + 1.f);
            s[nt][2] = s[nt][2] * 0.125f - slope * c0;
            s[nt][3] = s[nt][3] * 0.125f - slope * (c0 + 1.f);
            if (diag) {
                if (jc > rowg0) s[nt][0] = -1e30f;
                if (jc + 1 > rowg0) s[nt][1] = -1e30f;
                if (jc > rowg1) s[nt][2] = -1e30f;
                if (jc + 1 > rowg1) s[nt][3] = -1e30f;
            }
            mx0 = fmaxf(mx0, fmaxf(s[nt][0], s[nt][1]));
            mx1 = fmaxf(mx1, fmaxf(s[nt][2], s[nt][3]));
        }
        mx0 = fmaxf(mx0, __shfl_xor_sync(0xffffffffu, mx0, 1, 4));
        mx0 = fmaxf(mx0, __shfl_xor_sync(0xffffffffu, mx0, 2, 4));
        mx1 = fmaxf(mx1, __shfl_xor_sync(0xffffffffu, mx1, 1, 4));
        mx1 = fmaxf(mx1, __shfl_xor_sync(0xffffffffu, mx1, 2, 4));
        const float mn0 = fmaxf(m0, mx0), mn1 = fmaxf(m1, mx1);
        const float cr0 = __expf(m0 - mn0), cr1 = __expf(m1 - mn1);
        m0 = mn0;
        m1 = mn1;
        float sum0 = 0.f, sum1 = 0.f;
#pragma unroll
        for (int nt = 0; nt < 16; ++nt) {
            s[nt][0] = __expf(s[nt][0] - mn0);
            s[nt][1] = __expf(s[nt][1] - mn0);
            s[nt][2] = __expf(s[nt][2] - mn1);
            s[nt][3] = __expf(s[nt][3] - mn1);
            sum0 += s[nt][0] + s[nt][1];
            sum1 += s[nt][2] + s[nt][3];
        }
        sum0 += __shfl_xor_sync(0xffffffffu, sum0, 1, 4);
        sum0 += __shfl_xor_sync(0xffffffffu, sum0, 2, 4);
        sum1 += __shfl_xor_sync(0xffffffffu, sum1, 1, 4);
        sum1 += __shfl_xor_sync(0xffffffffu, sum1, 2, 4);
        l0 = l0 * cr0 + sum0;
        l1 = l1 * cr1 + sum1;
#pragma unroll
        for (int nt = 0; nt < 8; ++nt) {
            o[nt][0] *= cr0;
            o[nt][1] *= cr0;
            o[nt][2] *= cr1;
            o[nt][3] *= cr1;
        }

        // ---- O += P V (3-term hi/lo; P from registers) ----
#pragma unroll
        for (int k16 = 0; k16 < 8; ++k16) {
            uint32_t ph[4], pl[4];
            pack_hilo(s[2 * k16][0], s[2 * k16][1], ph[0], pl[0]);
            pack_hilo(s[2 * k16][2], s[2 * k16][3], ph[1], pl[1]);
            pack_hilo(s[2 * k16 + 1][0], s[2 * k16 + 1][1], ph[2], pl[2]);
            pack_hilo(s[2 * k16 + 1][2], s[2 * k16 + 1][3], ph[3], pl[3]);
            const int row = k16 * 16 + (q & 1) * 8 + r;
#pragma unroll
            for (int cgp = 0; cgp < 4; ++cgp) {
                const int c = cgp * 2 + (q >> 1);
                uint32_t ad = sv + row * 128 + ((c ^ r) << 4);
                uint32_t vh[4], vl[4];
                ldsm4t(vh, ad);
                ldsm4t(vl, ad + 16384);
                mma16816(o[cgp * 2], ph, vh);
                mma16816(o[cgp * 2], ph, vl);
                mma16816(o[cgp * 2], pl, vh);
                mma16816(o[cgp * 2 + 1], ph, vh + 2);
                mma16816(o[cgp * 2 + 1], ph, vl + 2);
                mma16816(o[cgp * 2 + 1], pl, vh + 2);
            }
        }
        __syncthreads();
        buf ^= 1;
    }

    // ---- epilogue: normalize, split hi/lo, store bf16 ----
    const float inv0 = 1.f / l0, inv1 = 1.f / l1;
    const size_t orow0 = (size_t)(qrow_base + w * 16 + g) * DIM + hcol;
    const size_t orow1 = orow0 + (size_t)8 * DIM;
#pragma unroll
    for (int nt = 0; nt < 8; ++nt) {
        const int col = nt * 8 + 2 * t;
        uint32_t hi, lo;
        pack_hilo(o[nt][0] * inv0, o[nt][1] * inv0, hi, lo);
        *(uint32_t*)&gOh[orow0 + col] = hi;
        *(uint32_t*)&gOl[orow0 + col] = lo;
        pack_hilo(o[nt][2] * inv1, o[nt][3] * inv1, hi, lo);
        *(uint32_t*)&gOh[orow1 + col] = hi;
        *(uint32_t*)&gOl[orow1 + col] = lo;
    }
}

// ---------------------------------------------------------------------------
extern "C" void kernel_launch(void* const* d_in, const int* in_sizes, int n_in,
                              void* d_out, int out_size) {
    const float* X  = (const float*)d_in[0];
    const float* Wq = (const float*)d_in[1];
    const float* bq = (const float*)d_in[2];
    const float* Wk = (const float*)d_in[3];
    const float* bk = (const float*)d_in[4];
    const float* Wv = (const float*)d_in[5];
    const float* Wo = (const float*)d_in[6];
    const float* bo = (const float*)d_in[7];
    float* out = (float*)d_out;

    cudaFuncSetAttribute(qkv_mma, cudaFuncAttributeMaxDynamicSharedMemorySize, GEMM_SMEM);
    cudaFuncSetAttribute(out_mma, cudaFuncAttributeMaxDynamicSharedMemorySize, GEMM_SMEM);
    cudaFuncSetAttribute(attn_mma, cudaFuncAttributeMaxDynamicSharedMemorySize, ATTN_SMEM);

    convert_inputs<<<2048, 256>>>(X, Wq, Wk, Wv, Wo);
    qkv_mma<<<dim3(DIM / 128, MROWS / 128, 3), 256, GEMM_SMEM>>>(bq, bk);
    attn_mma<<<dim3(SEQ / 128, BQ * NH), 256, ATTN_SMEM>>>();
    out_mma<<<dim3(DIM / 128, MROWS / 128, 1), 256, GEMM_SMEM>>>(bo, out);
}

// round 5
// speedup vs baseline: 3.1034x; 1.0798x over previous
#include <cuda_runtime.h>
#include <cuda_fp16.h>
#include <math.h>
#include <stdint.h>

// Problem constants
#define BQ   2
#define SEQ  2048
#define DIM  1024
#define NH   16
#define HDIM 64
#define MROWS (BQ * SEQ)   // 4096

#define C63 0.984375f      // 63/64
#define CINV64 0.015625f   // 1/64

// Scratch (device globals). h = fp16 main, m = fp16 merged-residual.
__device__ __half gXh[MROWS * DIM];
__device__ __half gXm[MROWS * DIM];
__device__ __half gWh[4 * DIM * DIM];
__device__ __half gWm[4 * DIM * DIM];
__device__ __half gQh[MROWS * DIM];
__device__ __half gQm[MROWS * DIM];
__device__ __half gKh[MROWS * DIM];
__device__ __half gKm[MROWS * DIM];
__device__ __half gVh[MROWS * DIM];
__device__ __half gVm[MROWS * DIM];
__device__ __half gOh[MROWS * DIM];
__device__ __half gOm[MROWS * DIM];

// ---------------------------------------------------------------------------
// Helpers
// ---------------------------------------------------------------------------
__device__ __forceinline__ uint32_t smem_u32(const void* p) {
    uint32_t a;
    asm("{ .reg .u64 t; cvta.to.shared.u64 t, %1; cvt.u32.u64 %0, t; }"
        : "=r"(a) : "l"(p));
    return a;
}
__device__ __forceinline__ void cp16(uint32_t dst, const void* src) {
    asm volatile("cp.async.cg.shared.global [%0], [%1], 16;"
                 :: "r"(dst), "l"(__cvta_generic_to_global(src)));
}
__device__ __forceinline__ void cp_commit() {
    asm volatile("cp.async.commit_group;" ::: "memory");
}
__device__ __forceinline__ void ldsm4(uint32_t* r, uint32_t addr) {
    asm volatile("ldmatrix.sync.aligned.m8n8.x4.shared.b16 {%0,%1,%2,%3}, [%4];"
                 : "=r"(r[0]), "=r"(r[1]), "=r"(r[2]), "=r"(r[3]) : "r"(addr));
}
__device__ __forceinline__ void ldsm4t(uint32_t* r, uint32_t addr) {
    asm volatile("ldmatrix.sync.aligned.m8n8.x4.trans.shared.b16 {%0,%1,%2,%3}, [%4];"
                 : "=r"(r[0]), "=r"(r[1]), "=r"(r[2]), "=r"(r[3]) : "r"(addr));
}
__device__ __forceinline__ void mma16816(float* c, const uint32_t* a, const uint32_t* b) {
    asm volatile(
        "mma.sync.aligned.m16n8k16.row.col.f32.f16.f16.f32 "
        "{%0,%1,%2,%3}, {%4,%5,%6,%7}, {%8,%9}, {%0,%1,%2,%3};"
        : "+f"(c[0]), "+f"(c[1]), "+f"(c[2]), "+f"(c[3])
        : "r"(a[0]), "r"(a[1]), "r"(a[2]), "r"(a[3]), "r"(b[0]), "r"(b[1]));
}
__device__ __forceinline__ uint32_t pack_h2(__half a, __half b) {
    __half2 t = __halves2half2(a, b);
    return *(uint32_t*)&t;
}
// A-side split: h = fp16(x), m = fp16(h + 64*(x-h))
__device__ __forceinline__ void splitA(float f0, float f1, uint32_t& h, uint32_t& m) {
    __half h0 = __float2half_rn(f0), h1 = __float2half_rn(f1);
    float r0 = f0 - __half2float(h0), r1 = f1 - __half2float(h1);
    __half m0 = __float2half_rn(fmaf(64.f, r0, __half2float(h0)));
    __half m1 = __float2half_rn(fmaf(64.f, r1, __half2float(h1)));
    h = pack_h2(h0, h1);
    m = pack_h2(m0, m1);
}
// B-side split: h = fp16(x), m = fp16((x-h) + h/64)
__device__ __forceinline__ void splitB(float f0, float f1, uint32_t& h, uint32_t& m) {
    __half h0 = __float2half_rn(f0), h1 = __float2half_rn(f1);
    float r0 = f0 - __half2float(h0), r1 = f1 - __half2float(h1);
    __half m0 = __float2half_rn(fmaf(__half2float(h0), CINV64, r0));
    __half m1 = __float2half_rn(fmaf(__half2float(h1), CINV64, r1));
    h = pack_h2(h0, h1);
    m = pack_h2(m0, m1);
}

// ---------------------------------------------------------------------------
// Convert fp32 inputs -> fp16 h/m pairs. X: A-side. Weights: B-side.
// ---------------------------------------------------------------------------
__global__ __launch_bounds__(256) void convert_inputs(
    const float* __restrict__ X, const float* __restrict__ Wq,
    const float* __restrict__ Wk, const float* __restrict__ Wv,
    const float* __restrict__ Wo) {
    const int XQ = MROWS * DIM / 4;
    const int WQ = DIM * DIM / 4;
    const int total4 = XQ + 4 * WQ;
    for (int i = blockIdx.x * blockDim.x + threadIdx.x; i < total4;
         i += gridDim.x * blockDim.x) {
        const float* src;
        __half *dh, *dm;
        bool aside;
        if (i < XQ) {
            int e = i * 4;
            src = X + e; dh = gXh + e; dm = gXm + e; aside = true;
        } else {
            int t = i - XQ;
            int w = t / WQ;
            int off = (t - w * WQ) * 4;
            src = (w == 0) ? Wq + off : (w == 1) ? Wk + off
                  : (w == 2) ? Wv + off : Wo + off;
            dh = gWh + (size_t)w * DIM * DIM + off;
            dm = gWm + (size_t)w * DIM * DIM + off;
            aside = false;
        }
        float4 v = *(const float4*)src;
        uint32_t h0, m0, h1, m1;
        if (aside) {
            splitA(v.x, v.y, h0, m0);
            splitA(v.z, v.w, h1, m1);
        } else {
            splitB(v.x, v.y, h0, m0);
            splitB(v.z, v.w, h1, m1);
        }
        ((uint32_t*)dh)[0] = h0;
        ((uint32_t*)dh)[1] = h1;
        ((uint32_t*)dm)[0] = m0;
        ((uint32_t*)dm)[1] = m1;
    }
}

// ---------------------------------------------------------------------------
// Tensor-core GEMM (merged 2-MMA fp16): 128x128 CTA tile, K-step 32,
// 8 warps (2m x 4n), 3-stage cp.async.
// Result: C = C1*(63/64) + C2 where C1 = Ah*Bh, C2 = Am*Bm.
// ---------------------------------------------------------------------------
#define STAGE_BYTES 32768
#define SM_BH 16384
#define SM_BM 24576
#define GEMM_SMEM (3 * STAGE_BYTES)

__device__ __forceinline__ void gemm_fill(uint32_t sbuf,
                                          const __half* __restrict__ Ah,
                                          const __half* __restrict__ Am,
                                          const __half* __restrict__ Bh,
                                          const __half* __restrict__ Bm,
                                          int row0, int col0, int kt, int tid) {
#pragma unroll
    for (int i = 0; i < 4; ++i) {  // A: 128 rows x 128B (h: c<4, m: c>=4)
        int lin = tid + i * 256;
        int m = lin >> 3, c = lin & 7;
        const __half* src =
            ((c < 4) ? Ah : Am) + (size_t)(row0 + m) * DIM + kt + (c & 3) * 8;
        uint32_t dst = sbuf + m * 128 + ((c ^ (m & 7)) << 4);
        cp16(dst, src);
    }
#pragma unroll
    for (int i = 0; i < 4; ++i) {  // B: 32 k-rows x 256B, h + m tiles
        int lin = tid + i * 256;
        int tile = lin >> 9, rem = lin & 511;
        int k = rem >> 4, c = rem & 15;
        const __half* src =
            (tile ? Bm : Bh) + (size_t)(kt + k) * DIM + col0 + c * 8;
        uint32_t dst = sbuf + (tile ? SM_BM : SM_BH) + k * 256 +
                       ((c >> 3) << 7) + (((c & 7) ^ (k & 7)) << 4);
        cp16(dst, src);
    }
}

__device__ __forceinline__ void mma_gemm_body(
    const __half* __restrict__ Ah_g, const __half* __restrict__ Am_g,
    const __half* __restrict__ Bh_g, const __half* __restrict__ Bm_g,
    const float* __restrict__ bias, float* __restrict__ Yf,
    __half* __restrict__ Yh, __half* __restrict__ Ym, int aside_out) {
    extern __shared__ __align__(1024) char smem[];
    const uint32_t sb = smem_u32(smem);
    const int tid = threadIdx.x;
    const int row0 = blockIdx.y * 128, col0 = blockIdx.x * 128;
    const int lane = tid & 31, wid = tid >> 5;
    const int wm = wid & 1, wn = wid >> 1;
    const int q = lane >> 3, r = lane & 7;
    const int arow = (q & 1) * 8 + r;
    const int aq = q >> 1;

    float acc1[4][4][4], acc2[4][4][4];
#pragma unroll
    for (int mt = 0; mt < 4; ++mt)
#pragma unroll
        for (int nt = 0; nt < 4; ++nt)
#pragma unroll
            for (int e = 0; e < 4; ++e) {
                acc1[mt][nt][e] = 0.f;
                acc2[mt][nt][e] = 0.f;
            }

    gemm_fill(sb, Ah_g, Am_g, Bh_g, Bm_g, row0, col0, 0, tid);
    cp_commit();
    gemm_fill(sb + STAGE_BYTES, Ah_g, Am_g, Bh_g, Bm_g, row0, col0, 32, tid);
    cp_commit();

    for (int s = 0; s < 32; ++s) {
        const int buf = s % 3;
        if (s + 2 < 32) {
            gemm_fill(sb + ((s + 2) % 3) * STAGE_BYTES, Ah_g, Am_g, Bh_g, Bm_g,
                      row0, col0, (s + 2) * 32, tid);
            cp_commit();
            asm volatile("cp.async.wait_group 2;" ::: "memory");
        } else if (s + 1 < 32) {
            asm volatile("cp.async.wait_group 1;" ::: "memory");
        } else {
            asm volatile("cp.async.wait_group 0;" ::: "memory");
        }
        __syncthreads();

        const uint32_t sA = sb + buf * STAGE_BYTES;
        const uint32_t sBh = sA + SM_BH;
        const uint32_t sBm = sA + SM_BM;

#pragma unroll
        for (int k16 = 0; k16 < 2; ++k16) {
            uint32_t bh[8], bm[8];
            {
                const int krow = k16 * 16 + (q & 1) * 8 + r;
#pragma unroll
                for (int g2 = 0; g2 < 2; ++g2) {
                    int cg = wn * 4 + g2 * 2 + (q >> 1);
                    uint32_t baddr = krow * 256 + ((cg >> 3) << 7) +
                                     (((cg & 7) ^ (krow & 7)) << 4);
                    ldsm4t(&bh[g2 * 4], sBh + baddr);
                    ldsm4t(&bm[g2 * 4], sBm + baddr);
                }
            }
            uint32_t ah[4][4], am[4][4];
#pragma unroll
            for (int mt = 0; mt < 4; ++mt) {
                int row = wm * 64 + mt * 16 + arow;
                int c1 = k16 * 2 + aq;
                int c2 = 4 + k16 * 2 + aq;
                ldsm4(ah[mt], sA + row * 128 + ((c1 ^ r) << 4));
                ldsm4(am[mt], sA + row * 128 + ((c2 ^ r) << 4));
            }
#pragma unroll
            for (int mt = 0; mt < 4; ++mt)
#pragma unroll
                for (int nt = 0; nt < 4; ++nt) {
                    const uint32_t* bph = &bh[(nt >> 1) * 4 + (nt & 1) * 2];
                    const uint32_t* bpm = &bm[(nt >> 1) * 4 + (nt & 1) * 2];
                    mma16816(acc1[mt][nt], ah[mt], bph);
                    mma16816(acc2[mt][nt], am[mt], bpm);
                }
        }
        __syncthreads();
    }

    const int cg = lane >> 2, ct = lane & 3;
#pragma unroll
    for (int mt = 0; mt < 4; ++mt) {
        int r0 = row0 + wm * 64 + mt * 16 + cg;
#pragma unroll
        for (int nt = 0; nt < 4; ++nt) {
            int col = col0 + wn * 32 + nt * 8 + ct * 2;
            float b0 = bias ? bias[col] : 0.f;
            float b1 = bias ? bias[col + 1] : 0.f;
            float v00 = fmaf(acc1[mt][nt][0], C63, acc2[mt][nt][0]) + b0;
            float v01 = fmaf(acc1[mt][nt][1], C63, acc2[mt][nt][1]) + b1;
            float v10 = fmaf(acc1[mt][nt][2], C63, acc2[mt][nt][2]) + b0;
            float v11 = fmaf(acc1[mt][nt][3], C63, acc2[mt][nt][3]) + b1;
            if (Yf) {
                *(float2*)(Yf + (size_t)r0 * DIM + col) = make_float2(v00, v01);
                *(float2*)(Yf + (size_t)(r0 + 8) * DIM + col) = make_float2(v10, v11);
            } else {
                uint32_t h, m;
                if (aside_out) splitA(v00, v01, h, m); else splitB(v00, v01, h, m);
                *(uint32_t*)&Yh[(size_t)r0 * DIM + col] = h;
                *(uint32_t*)&Ym[(size_t)r0 * DIM + col] = m;
                if (aside_out) splitA(v10, v11, h, m); else splitB(v10, v11, h, m);
                *(uint32_t*)&Yh[(size_t)(r0 + 8) * DIM + col] = h;
                *(uint32_t*)&Ym[(size_t)(r0 + 8) * DIM + col] = m;
            }
        }
    }
}

__global__ __launch_bounds__(256, 1) void qkv_mma(const float* __restrict__ bq,
                                                  const float* __restrict__ bk) {
    const int z = blockIdx.z;
    const __half* Bh = gWh + (size_t)z * DIM * DIM;
    const __half* Bm = gWm + (size_t)z * DIM * DIM;
    const float* bias = (z == 0) ? bq : (z == 1) ? bk : nullptr;
    __half* Yh = (z == 0) ? gQh : (z == 1) ? gKh : gVh;
    __half* Ym = (z == 0) ? gQm : (z == 1) ? gKm : gVm;
    // Q is consumed as an A operand; K and V as B operands.
    mma_gemm_body(gXh, gXm, Bh, Bm, bias, nullptr, Yh, Ym, z == 0 ? 1 : 0);
}

__global__ __launch_bounds__(256, 1) void out_mma(const float* __restrict__ bo,
                                                  float* __restrict__ out) {
    mma_gemm_body(gOh, gOm, gWh + (size_t)3 * DIM * DIM,
                  gWm + (size_t)3 * DIM * DIM, bo, out, nullptr, nullptr, 0);
}

// ---------------------------------------------------------------------------
// Flash attention on tensor cores (merged 2-MMA fp16).
// 8 warps; warp w owns 16 query rows of a 128-row i-tile.
// Stochastic soft mask (mean -1e9, std 1e8) underflows exp() -> hard causal.
// smem: Qh/Qm [128][64] + 2 stages of {Kh,Km,Vh,Vm}[128][64].
// ---------------------------------------------------------------------------
#define A_ST0 32768
#define A_STAGE 65536
#define ATTN_SMEM (32768 + 2 * 65536)

__global__ __launch_bounds__(256, 1) void attn_mma() {
    extern __shared__ __align__(1024) char smem[];
    const uint32_t sb = smem_u32(smem);
    const int tid = threadIdx.x;
    const int lane = tid & 31, w = tid >> 5;
    const int q = lane >> 3, r = lane & 7;
    const int g = lane >> 2, t = lane & 3;
    const int it = 15 - (int)blockIdx.x;  // heavy tiles first
    const int bh = blockIdx.y;
    const int b = bh >> 4, h = bh & 15;
    const int i0 = it * 128;
    const float slope = exp2f(-0.5f * (float)(h + 1));
    const int qrow_base = b * SEQ + i0;
    const int hcol = h * HDIM;

    // ---- fill Q (h+m) ----
#pragma unroll
    for (int i = 0; i < 8; ++i) {
        int lin = tid + i * 256;
        int tz = lin >> 10;
        int rem = lin & 1023;
        int m = rem >> 3, c = rem & 7;
        const __half* src =
            (tz ? gQm : gQh) + (size_t)(qrow_base + m) * DIM + hcol + c * 8;
        cp16(sb + tz * 16384 + m * 128 + ((c ^ (m & 7)) << 4), src);
    }
    // ---- fill K/V stage 0 ----
    {
        const int krow_base = b * SEQ;
#pragma unroll
        for (int i = 0; i < 16; ++i) {
            int lin = tid + i * 256;
            int tz = lin >> 10;  // 0=Kh 1=Km 2=Vh 3=Vm
            int rem = lin & 1023;
            int m = rem >> 3, c = rem & 7;
            const __half* src =
                ((tz == 0) ? gKh : (tz == 1) ? gKm : (tz == 2) ? gVh : gVm) +
                (size_t)(krow_base + m) * DIM + hcol + c * 8;
            cp16(sb + A_ST0 + tz * 16384 + m * 128 + ((c ^ (m & 7)) << 4), src);
        }
    }
    cp_commit();

    float o1[8][4], o2[8][4];
#pragma unroll
    for (int nt = 0; nt < 8; ++nt)
#pragma unroll
        for (int e = 0; e < 4; ++e) {
            o1[nt][e] = 0.f;
            o2[nt][e] = 0.f;
        }
    float m0 = -1e30f, m1 = -1e30f, l0 = 0.f, l1 = 0.f;
    uint32_t qh[4][4], qm[4][4];

    int buf = 0;
    for (int jt = 0; jt <= it; ++jt) {
        if (jt < it) {
            const int krow_base = b * SEQ + (jt + 1) * 128;
            const uint32_t st = sb + A_ST0 + (buf ^ 1) * A_STAGE;
#pragma unroll
            for (int i = 0; i < 16; ++i) {
                int lin = tid + i * 256;
                int tz = lin >> 10;
                int rem = lin & 1023;
                int m = rem >> 3, c = rem & 7;
                const __half* src =
                    ((tz == 0) ? gKh : (tz == 1) ? gKm : (tz == 2) ? gVh : gVm) +
                    (size_t)(krow_base + m) * DIM + hcol + c * 8;
                cp16(st + tz * 16384 + m * 128 + ((c ^ (m & 7)) << 4), src);
            }
            cp_commit();
            asm volatile("cp.async.wait_group 1;" ::: "memory");
        } else {
            asm volatile("cp.async.wait_group 0;" ::: "memory");
        }
        __syncthreads();

        if (jt == 0) {  // hoist Q fragments into registers
#pragma unroll
            for (int k16 = 0; k16 < 4; ++k16) {
                int row = w * 16 + (q & 1) * 8 + r;
                int c = k16 * 2 + (q >> 1);
                uint32_t ad = sb + row * 128 + ((c ^ r) << 4);
                ldsm4(qh[k16], ad);
                ldsm4(qm[k16], ad + 16384);
            }
        }

        const uint32_t sk = sb + A_ST0 + buf * A_STAGE;
        const uint32_t sv = sk + 32768;

        // ---- S = Q K^T (merged 2-MMA), strip-by-strip to bound registers ----
        float s[16][4];
#pragma unroll
        for (int nt16 = 0; nt16 < 8; ++nt16) {
            float s1[2][4], s2[2][4];
#pragma unroll
            for (int e = 0; e < 4; ++e) {
                s1[0][e] = s1[1][e] = 0.f;
                s2[0][e] = s2[1][e] = 0.f;
            }
            const int row = nt16 * 16 + (q >> 1) * 8 + r;
#pragma unroll
            for (int k16 = 0; k16 < 4; ++k16) {
                const int c = k16 * 2 + (q & 1);
                uint32_t ad = sk + row * 128 + ((c ^ r) << 4);
                uint32_t kh[4], km[4];
                ldsm4(kh, ad);
                ldsm4(km, ad + 16384);
                mma16816(s1[0], qh[k16], kh);
                mma16816(s2[0], qm[k16], km);
                mma16816(s1[1], qh[k16], kh + 2);
                mma16816(s2[1], qm[k16], km + 2);
            }
#pragma unroll
            for (int e = 0; e < 4; ++e) {
                s[2 * nt16][e] = fmaf(s1[0][e], C63, s2[0][e]);
                s[2 * nt16 + 1][e] = fmaf(s1[1][e], C63, s2[1][e]);
            }
        }

        // ---- online softmax ----
        const int j0 = jt * 128;
        const int rowg0 = i0 + w * 16 + g;
        const int rowg1 = rowg0 + 8;
        const bool diag = (jt == it);
        float mx0 = -1e30f, mx1 = -1e30f;
#pragma unroll
        for (int nt = 0; nt < 16; ++nt) {
            const int jc = j0 + nt * 8 + 2 * t;
            const float c0 = (float)jc;
            s[nt][0] = s[nt][0] * 0.125f - slope * c0;
            s[nt][1] = s[nt][1] * 0.125f - slope * (c0 + 1.f);
            s[nt][2] = s[nt][2] * 0.125f - slope * c0;
            s[nt][3] = s[nt][3] * 0.125f - slope * (c0 + 1.f);
            if (diag) {
                if (jc > rowg0) s[nt][0] = -1e30f;
                if (jc + 1 > rowg0) s[nt][1] = -1e30f;
                if (jc > rowg1) s[nt][2] = -1e30f;
                if (jc + 1 > rowg1) s[nt][3] = -1e30f;
            }
            mx0 = fmaxf(mx0, fmaxf(s[nt][0], s[nt][1]));
            mx1 = fmaxf(mx1, fmaxf(s[nt][2], s[nt][3]));
        }
        mx0 = fmaxf(mx0, __shfl_xor_sync(0xffffffffu, mx0, 1, 4));
        mx0 = fmaxf(mx0, __shfl_xor_sync(0xffffffffu, mx0, 2, 4));
        mx1 = fmaxf(mx1, __shfl_xor_sync(0xffffffffu, mx1, 1, 4));
        mx1 = fmaxf(mx1, __shfl_xor_sync(0xffffffffu, mx1, 2, 4));
        const float mn0 = fmaxf(m0, mx0), mn1 = fmaxf(m1, mx1);
        const float cr0 = __expf(m0 - mn0), cr1 = __expf(m1 - mn1);
        m0 = mn0;
        m1 = mn1;
        float sum0 = 0.f, sum1 = 0.f;
#pragma unroll
        for (int nt = 0; nt < 16; ++nt) {
            s[nt][0] = __expf(s[nt][0] - mn0);
            s[nt][1] = __expf(s[nt][1] - mn0);
            s[nt][2] = __expf(s[nt][2] - mn1);
            s[nt][3] = __expf(s[nt][3] - mn1);
            sum0 += s[nt][0] + s[nt][1];
            sum1 += s[nt][2] + s[nt][3];
        }
        sum0 += __shfl_xor_sync(0xffffffffu, sum0, 1, 4);
        sum0 += __shfl_xor_sync(0xffffffffu, sum0, 2, 4);
        sum1 += __shfl_xor_sync(0xffffffffu, sum1, 1, 4);
        sum1 += __shfl_xor_sync(0xffffffffu, sum1, 2, 4);
        l0 = l0 * cr0 + sum0;
        l1 = l1 * cr1 + sum1;
#pragma unroll
        for (int nt = 0; nt < 8; ++nt) {
            o1[nt][0] *= cr0; o1[nt][1] *= cr0;
            o1[nt][2] *= cr1; o1[nt][3] *= cr1;
            o2[nt][0] *= cr0; o2[nt][1] *= cr0;
            o2[nt][2] *= cr1; o2[nt][3] *= cr1;
        }

        // ---- O += P V (merged 2-MMA; P A-side from registers) ----
#pragma unroll
        for (int k16 = 0; k16 < 8; ++k16) {
            uint32_t ph[4], pm[4];
            splitA(s[2 * k16][0], s[2 * k16][1], ph[0], pm[0]);
            splitA(s[2 * k16][2], s[2 * k16][3], ph[1], pm[1]);
            splitA(s[2 * k16 + 1][0], s[2 * k16 + 1][1], ph[2], pm[2]);
            splitA(s[2 * k16 + 1][2], s[2 * k16 + 1][3], ph[3], pm[3]);
            const int row = k16 * 16 + (q & 1) * 8 + r;
#pragma unroll
            for (int cgp = 0; cgp < 4; ++cgp) {
                const int c = cgp * 2 + (q >> 1);
                uint32_t ad = sv + row * 128 + ((c ^ r) << 4);
                uint32_t vh[4], vm[4];
                ldsm4t(vh, ad);
                ldsm4t(vm, ad + 16384);
                mma16816(o1[cgp * 2], ph, vh);
                mma16816(o2[cgp * 2], pm, vm);
                mma16816(o1[cgp * 2 + 1], ph, vh + 2);
                mma16816(o2[cgp * 2 + 1], pm, vm + 2);
            }
        }
        __syncthreads();
        buf ^= 1;
    }

    // ---- epilogue: combine, normalize, split A-side, store ----
    const float inv0 = 1.f / l0, inv1 = 1.f / l1;
    const size_t orow0 = (size_t)(qrow_base + w * 16 + g) * DIM + hcol;
    const size_t orow1 = orow0 + (size_t)8 * DIM;
#pragma unroll
    for (int nt = 0; nt < 8; ++nt) {
        const int col = nt * 8 + 2 * t;
        float f0 = fmaf(o1[nt][0], C63, o2[nt][0]) * inv0;
        float f1 = fmaf(o1[nt][1], C63, o2[nt][1]) * inv0;
        float f2 = fmaf(o1[nt][2], C63, o2[nt][2]) * inv1;
        float f3 = fmaf(o1[nt][3], C63, o2[nt][3]) * inv1;
        uint32_t hh, mm;
        splitA(f0, f1, hh, mm);
        *(uint32_t*)&gOh[orow0 + col] = hh;
        *(uint32_t*)&gOm[orow0 + col] = mm;
        splitA(f2, f3, hh, mm);
        *(uint32_t*)&gOh[orow1 + col] = hh;
        *(uint32_t*)&gOm[orow1 + col] = mm;
    }
}

// ---------------------------------------------------------------------------
extern "C" void kernel_launch(void* const* d_in, const int* in_sizes, int n_in,
                              void* d_out, int out_size) {
    const float* X  = (const float*)d_in[0];
    const float* Wq = (const float*)d_in[1];
    const float* bq = (const float*)d_in[2];
    const float* Wk = (const float*)d_in[3];
    const float* bk = (const float*)d_in[4];
    const float* Wv = (const float*)d_in[5];
    const float* Wo = (const float*)d_in[6];
    const float* bo = (const float*)d_in[7];
    float* out = (float*)d_out;

    cudaFuncSetAttribute(qkv_mma, cudaFuncAttributeMaxDynamicSharedMemorySize, GEMM_SMEM);
    cudaFuncSetAttribute(out_mma, cudaFuncAttributeMaxDynamicSharedMemorySize, GEMM_SMEM);
    cudaFuncSetAttribute(attn_mma, cudaFuncAttributeMaxDynamicSharedMemorySize, ATTN_SMEM);

    convert_inputs<<<2048, 256>>>(X, Wq, Wk, Wv, Wo);
    qkv_mma<<<dim3(DIM / 128, MROWS / 128, 3), 256, GEMM_SMEM>>>(bq, bk);
    attn_mma<<<dim3(SEQ / 128, BQ * NH), 256, ATTN_SMEM>>>();
    out_mma<<<dim3(DIM / 128, MROWS / 128, 1), 256, GEMM_SMEM>>>(bo, out);
}